// round 2
// baseline (speedup 1.0000x reference)
#include <cuda_runtime.h>

#define NT      17
#define DIN     128
#define H1D     128
#define DOUTD   128
#define NNODES  32768
#define ROWS    64
#define MAX_TILES (NNODES / ROWS)   // 512

// Scratch (allocation-free per harness rules)
__device__ int g_count[NT];
__device__ int g_idx[NT * NNODES];

__global__ void zero_counts_kernel() {
    if (threadIdx.x < NT) g_count[threadIdx.x] = 0;
}

__global__ void scatter_kernel(const int* __restrict__ types) {
    int n = blockIdx.x * blockDim.x + threadIdx.x;
    if (n < NNODES) {
        int t = types[n];
        int p = atomicAdd(&g_count[t], 1);
        g_idx[t * NNODES + p] = n;
    }
}

// One block = (expert t, tile of up to 64 nodes of that type).
// 256 threads (16x16), each computes a 4(m) x 8(n) fp32 micro-tile.
// Layer1 -> relu -> hidden written back into the same smem buffer -> Layer2.
__global__ __launch_bounds__(256) void mlp_kernel(
    const float* __restrict__ x,
    const float* __restrict__ W1,
    const float* __restrict__ b1,
    const float* __restrict__ W2,
    const float* __restrict__ b2,
    float* __restrict__ out)
{
    const int t    = blockIdx.y;
    const int cnt  = g_count[t];
    const int base = blockIdx.x * ROWS;
    if (base >= cnt) return;

    __shared__ __align__(16) float S[ROWS][132];  // 132-float stride: 16B-aligned rows, no bank conflicts
    __shared__ int rowidx[ROWS];

    const int tid = threadIdx.x;
    if (tid < ROWS) {
        int r = base + tid;
        rowidx[tid] = (r < cnt) ? g_idx[t * NNODES + r] : -1;
    }
    __syncthreads();

    // Gather x rows for this tile: thread -> (row = tid/4, quarter = tid%4), 8 float4 each.
    {
        int r = tid >> 2;
        int q = tid & 3;
        int g = rowidx[r];
        #pragma unroll
        for (int i = 0; i < 8; i++) {
            int k = q * 32 + i * 4;
            float4 v = make_float4(0.f, 0.f, 0.f, 0.f);
            if (g >= 0) v = __ldg(reinterpret_cast<const float4*>(x + (size_t)g * DIN + k));
            *reinterpret_cast<float4*>(&S[r][k]) = v;
        }
    }
    __syncthreads();

    const int ty = tid >> 4;       // 0..15
    const int tx = tid & 15;       // 0..15
    const int n0 = tx * 8;
    const int m0 = ty * 4;

    float acc[4][8];

    // ---------------- Layer 1: H = relu(X @ W1 + b1) ----------------
    {
        const float* W1t = W1 + (size_t)t * DIN * H1D;
        #pragma unroll
        for (int mi = 0; mi < 4; mi++)
            #pragma unroll
            for (int ni = 0; ni < 8; ni++) acc[mi][ni] = 0.f;

        #pragma unroll 8
        for (int k = 0; k < DIN; k++) {
            float4 wA = __ldg(reinterpret_cast<const float4*>(W1t + k * H1D + n0));
            float4 wB = __ldg(reinterpret_cast<const float4*>(W1t + k * H1D + n0 + 4));
            float w[8] = {wA.x, wA.y, wA.z, wA.w, wB.x, wB.y, wB.z, wB.w};
            #pragma unroll
            for (int mi = 0; mi < 4; mi++) {
                float xv = S[m0 + mi][k];
                #pragma unroll
                for (int ni = 0; ni < 8; ni++) acc[mi][ni] += xv * w[ni];
            }
        }

        float4 bA = __ldg(reinterpret_cast<const float4*>(b1 + t * H1D + n0));
        float4 bB = __ldg(reinterpret_cast<const float4*>(b1 + t * H1D + n0 + 4));
        float bb[8] = {bA.x, bA.y, bA.z, bA.w, bB.x, bB.y, bB.z, bB.w};

        __syncthreads();   // all layer-1 reads of S complete before overwrite
        #pragma unroll
        for (int mi = 0; mi < 4; mi++) {
            float h[8];
            #pragma unroll
            for (int ni = 0; ni < 8; ni++) h[ni] = fmaxf(acc[mi][ni] + bb[ni], 0.f);
            *reinterpret_cast<float4*>(&S[m0 + mi][n0])     = make_float4(h[0], h[1], h[2], h[3]);
            *reinterpret_cast<float4*>(&S[m0 + mi][n0 + 4]) = make_float4(h[4], h[5], h[6], h[7]);
        }
        __syncthreads();
    }

    // ---------------- Layer 2: Y = H @ W2 + b2 ----------------
    {
        const float* W2t = W2 + (size_t)t * H1D * DOUTD;
        #pragma unroll
        for (int mi = 0; mi < 4; mi++)
            #pragma unroll
            for (int ni = 0; ni < 8; ni++) acc[mi][ni] = 0.f;

        #pragma unroll 8
        for (int k = 0; k < H1D; k++) {
            float4 wA = __ldg(reinterpret_cast<const float4*>(W2t + k * DOUTD + n0));
            float4 wB = __ldg(reinterpret_cast<const float4*>(W2t + k * DOUTD + n0 + 4));
            float w[8] = {wA.x, wA.y, wA.z, wA.w, wB.x, wB.y, wB.z, wB.w};
            #pragma unroll
            for (int mi = 0; mi < 4; mi++) {
                float hv = S[m0 + mi][k];
                #pragma unroll
                for (int ni = 0; ni < 8; ni++) acc[mi][ni] += hv * w[ni];
            }
        }

        float4 bA = __ldg(reinterpret_cast<const float4*>(b2 + t * DOUTD + n0));
        float4 bB = __ldg(reinterpret_cast<const float4*>(b2 + t * DOUTD + n0 + 4));
        float bb[8] = {bA.x, bA.y, bA.z, bA.w, bB.x, bB.y, bB.z, bB.w};

        #pragma unroll
        for (int mi = 0; mi < 4; mi++) {
            int g = rowidx[m0 + mi];
            if (g >= 0) {
                float y[8];
                #pragma unroll
                for (int ni = 0; ni < 8; ni++) y[ni] = acc[mi][ni] + bb[ni];
                float* op = out + (size_t)g * DOUTD + n0;
                *reinterpret_cast<float4*>(op)     = make_float4(y[0], y[1], y[2], y[3]);
                *reinterpret_cast<float4*>(op + 4) = make_float4(y[4], y[5], y[6], y[7]);
            }
        }
    }
}

extern "C" void kernel_launch(void* const* d_in, const int* in_sizes, int n_in,
                              void* d_out, int out_size)
{
    const float* x     = (const float*)d_in[0];
    const float* W1    = (const float*)d_in[1];
    const float* b1    = (const float*)d_in[2];
    const float* W2    = (const float*)d_in[3];
    const float* b2    = (const float*)d_in[4];
    const int*   types = (const int*)  d_in[5];
    float*       out   = (float*)d_out;

    zero_counts_kernel<<<1, 32>>>();
    scatter_kernel<<<NNODES / 256, 256>>>(types);
    dim3 grid(MAX_TILES, NT);
    mlp_kernel<<<grid, 256>>>(x, W1, b1, W2, b2, out);
}

// round 3
// speedup vs baseline: 2.7081x; 2.7081x over previous
#include <cuda_runtime.h>
#include <cstdint>

#define NT      17
#define DIN     128
#define H1D     128
#define DOUTD   128
#define NNODES  32768
#define ROWS    128
#define TILES   (NNODES / ROWS)   // 256

#define S_STRIDE 132   // X/H tile row stride (floats): conflict-free A-frag lds
#define W_STRIDE 136   // W slab row stride (floats): conflict-free B-frag lds

// smem layout (dynamic):
//  float S [128][132]        = 16896 floats
//  float Wh[2][8][136]       =  2176 floats
//  float Wl[2][8][136]       =  2176 floats
//  int   rowidx[128]
#define S_FLOATS   (ROWS * S_STRIDE)
#define WBUF_FLOATS (8 * W_STRIDE)
#define SMEM_BYTES ((S_FLOATS + 4 * WBUF_FLOATS) * 4 + ROWS * 4)

// ---------------- scratch (allocation-free) ----------------
__device__ int g_count[NT];
__device__ int g_idx[NT * NNODES];

__global__ void zero_counts_kernel() {
    if (threadIdx.x < NT) g_count[threadIdx.x] = 0;
}

__global__ void scatter_kernel(const int* __restrict__ types) {
    int n = blockIdx.x * blockDim.x + threadIdx.x;
    if (n < NNODES) {
        int t = types[n];
        int p = atomicAdd(&g_count[t], 1);
        g_idx[t * NNODES + p] = n;
    }
}

// ---------------- tf32 helpers ----------------
__device__ __forceinline__ uint32_t f2tf(float f) {
    uint32_t u;
    asm("cvt.rna.tf32.f32 %0, %1;" : "=r"(u) : "f"(f));
    return u;
}

__device__ __forceinline__ void mma_tf32(float* c, const uint32_t* a, const uint32_t* b) {
    asm volatile(
        "mma.sync.aligned.m16n8k8.row.col.f32.tf32.tf32.f32 "
        "{%0,%1,%2,%3}, {%4,%5,%6,%7}, {%8,%9}, {%0,%1,%2,%3};"
        : "+f"(c[0]), "+f"(c[1]), "+f"(c[2]), "+f"(c[3])
        : "r"(a[0]), "r"(a[1]), "r"(a[2]), "r"(a[3]), "r"(b[0]), "r"(b[1]));
}

// Stage one 8x128 W k-slab into smem as tf32 hi/lo (cooperative, 256 threads).
__device__ __forceinline__ void stage_slab(const float* __restrict__ Wt, int ks,
                                           float* WhB, float* WlB, int tid) {
    int row = tid >> 5;          // 0..7
    int col = (tid & 31) << 2;   // 0..124
    float4 w = __ldg(reinterpret_cast<const float4*>(Wt + (ks * 8 + row) * 128 + col));
    float4 hi, lo;
    hi.x = __uint_as_float(f2tf(w.x)); lo.x = __uint_as_float(f2tf(w.x - hi.x));
    hi.y = __uint_as_float(f2tf(w.y)); lo.y = __uint_as_float(f2tf(w.y - hi.y));
    hi.z = __uint_as_float(f2tf(w.z)); lo.z = __uint_as_float(f2tf(w.z - hi.z));
    hi.w = __uint_as_float(f2tf(w.w)); lo.w = __uint_as_float(f2tf(w.w - hi.w));
    *reinterpret_cast<float4*>(WhB + row * W_STRIDE + col) = hi;
    *reinterpret_cast<float4*>(WlB + row * W_STRIDE + col) = lo;
}

// One 128x128x128 GEMM: acc += S(tile) @ W, split-tf32 (3 cross products).
// Warp = 2 m-tiles (32 rows) x 8 n-tiles (64 cols).
__device__ __forceinline__ void gemm128(const float* __restrict__ Wt,
                                        const float* S, float* Wh, float* Wl,
                                        float acc[2][8][4],
                                        int tid, int lane, int mbase, int nbase) {
    stage_slab(Wt, 0, Wh, Wl, tid);
    __syncthreads();

    #pragma unroll 1
    for (int ks = 0; ks < 16; ks++) {
        int cur = ks & 1;
        if (ks + 1 < 16)
            stage_slab(Wt, ks + 1, Wh + (1 - cur) * WBUF_FLOATS,
                                   Wl + (1 - cur) * WBUF_FLOATS, tid);

        // A fragments (fp32 from smem -> tf32 hi/lo in regs)
        uint32_t ahi[2][4], alo[2][4];
        int acol = ks * 8 + (lane & 3);
        #pragma unroll
        for (int s = 0; s < 2; s++) {
            int r = mbase + s * 16 + (lane >> 2);
            float a0 = S[r * S_STRIDE + acol];
            float a1 = S[(r + 8) * S_STRIDE + acol];
            float a2 = S[r * S_STRIDE + acol + 4];
            float a3 = S[(r + 8) * S_STRIDE + acol + 4];
            ahi[s][0] = f2tf(a0); alo[s][0] = f2tf(a0 - __uint_as_float(ahi[s][0]));
            ahi[s][1] = f2tf(a1); alo[s][1] = f2tf(a1 - __uint_as_float(ahi[s][1]));
            ahi[s][2] = f2tf(a2); alo[s][2] = f2tf(a2 - __uint_as_float(ahi[s][2]));
            ahi[s][3] = f2tf(a3); alo[s][3] = f2tf(a3 - __uint_as_float(ahi[s][3]));
        }

        const float* WhC = Wh + cur * WBUF_FLOATS;
        const float* WlC = Wl + cur * WBUF_FLOATS;
        int brow = lane & 3;
        #pragma unroll
        for (int nt = 0; nt < 8; nt++) {
            int bcol = nbase + nt * 8 + (lane >> 2);
            uint32_t bh[2], bl[2];
            bh[0] = __float_as_uint(WhC[brow * W_STRIDE + bcol]);
            bh[1] = __float_as_uint(WhC[(brow + 4) * W_STRIDE + bcol]);
            bl[0] = __float_as_uint(WlC[brow * W_STRIDE + bcol]);
            bl[1] = __float_as_uint(WlC[(brow + 4) * W_STRIDE + bcol]);
            #pragma unroll
            for (int s = 0; s < 2; s++) {
                mma_tf32(acc[s][nt], ahi[s], bh);
                mma_tf32(acc[s][nt], ahi[s], bl);
                mma_tf32(acc[s][nt], alo[s], bh);
            }
        }
        __syncthreads();
    }
}

extern __shared__ __align__(16) float smem[];

__global__ __launch_bounds__(256, 2) void mlp_kernel(
    const float* __restrict__ x,
    const float* __restrict__ W1,
    const float* __restrict__ b1,
    const float* __restrict__ W2,
    const float* __restrict__ b2,
    float* __restrict__ out)
{
    float* S  = smem;
    float* Wh = S + S_FLOATS;
    float* Wl = Wh + 2 * WBUF_FLOATS;
    int* rowidx = reinterpret_cast<int*>(Wl + 2 * WBUF_FLOATS);

    const int t    = blockIdx.y;
    const int cnt  = g_count[t];
    const int base = blockIdx.x * ROWS;
    if (base >= cnt) return;

    const int tid  = threadIdx.x;
    const int lane = tid & 31;
    const int warp = tid >> 5;
    const int mbase = (warp >> 1) * 32;
    const int nbase = (warp & 1) * 64;

    if (tid < ROWS) {
        int r = base + tid;
        rowidx[tid] = (r < cnt) ? g_idx[t * NNODES + r] : -1;
    }
    __syncthreads();

    // Gather x rows into S (thread -> half a row via 16 float4s)
    {
        int r = tid >> 1, half = tid & 1;
        int g = rowidx[r];
        float4* dst = reinterpret_cast<float4*>(S + r * S_STRIDE + half * 64);
        if (g >= 0) {
            const float4* src = reinterpret_cast<const float4*>(x + (size_t)g * DIN + half * 64);
            #pragma unroll
            for (int i = 0; i < 16; i++) dst[i] = __ldg(src + i);
        } else {
            #pragma unroll
            for (int i = 0; i < 16; i++) dst[i] = make_float4(0.f, 0.f, 0.f, 0.f);
        }
    }
    // (sync inside gemm128 covers the gather)

    float acc[2][8][4];
    #pragma unroll
    for (int s = 0; s < 2; s++)
        #pragma unroll
        for (int nt = 0; nt < 8; nt++)
            #pragma unroll
            for (int i = 0; i < 4; i++) acc[s][nt][i] = 0.f;

    // ---------------- Layer 1 ----------------
    gemm128(W1 + (size_t)t * DIN * H1D, S, Wh, Wl, acc, tid, lane, mbase, nbase);

    // bias + relu -> write H back into S
    #pragma unroll
    for (int s = 0; s < 2; s++) {
        #pragma unroll
        for (int nt = 0; nt < 8; nt++) {
            int col = nbase + nt * 8 + 2 * (lane & 3);
            float bb0 = __ldg(b1 + t * H1D + col);
            float bb1 = __ldg(b1 + t * H1D + col + 1);
            int r0 = mbase + s * 16 + (lane >> 2);
            float2 v0 = make_float2(fmaxf(acc[s][nt][0] + bb0, 0.f),
                                    fmaxf(acc[s][nt][1] + bb1, 0.f));
            float2 v1 = make_float2(fmaxf(acc[s][nt][2] + bb0, 0.f),
                                    fmaxf(acc[s][nt][3] + bb1, 0.f));
            *reinterpret_cast<float2*>(S + r0 * S_STRIDE + col)       = v0;
            *reinterpret_cast<float2*>(S + (r0 + 8) * S_STRIDE + col) = v1;
            acc[s][nt][0] = acc[s][nt][1] = acc[s][nt][2] = acc[s][nt][3] = 0.f;
        }
    }
    // (sync inside second gemm128 orders these writes before reads)

    // ---------------- Layer 2 ----------------
    gemm128(W2 + (size_t)t * H1D * DOUTD, S, Wh, Wl, acc, tid, lane, mbase, nbase);

    // bias -> scatter to out
    #pragma unroll
    for (int s = 0; s < 2; s++) {
        #pragma unroll
        for (int nt = 0; nt < 8; nt++) {
            int col = nbase + nt * 8 + 2 * (lane & 3);
            float bb0 = __ldg(b2 + t * DOUTD + col);
            float bb1 = __ldg(b2 + t * DOUTD + col + 1);
            int r0 = mbase + s * 16 + (lane >> 2);
            int g0 = rowidx[r0];
            int g1 = rowidx[r0 + 8];
            if (g0 >= 0) {
                float2 v = make_float2(acc[s][nt][0] + bb0, acc[s][nt][1] + bb1);
                *reinterpret_cast<float2*>(out + (size_t)g0 * DOUTD + col) = v;
            }
            if (g1 >= 0) {
                float2 v = make_float2(acc[s][nt][2] + bb0, acc[s][nt][3] + bb1);
                *reinterpret_cast<float2*>(out + (size_t)g1 * DOUTD + col) = v;
            }
        }
    }
}

extern "C" void kernel_launch(void* const* d_in, const int* in_sizes, int n_in,
                              void* d_out, int out_size)
{
    const float* x     = (const float*)d_in[0];
    const float* W1    = (const float*)d_in[1];
    const float* b1    = (const float*)d_in[2];
    const float* W2    = (const float*)d_in[3];
    const float* b2    = (const float*)d_in[4];
    const int*   types = (const int*)  d_in[5];
    float*       out   = (float*)d_out;

    cudaFuncSetAttribute(mlp_kernel, cudaFuncAttributeMaxDynamicSharedMemorySize, SMEM_BYTES);

    zero_counts_kernel<<<1, 32>>>();
    scatter_kernel<<<NNODES / 256, 256>>>(types);
    dim3 grid(TILES, NT);
    mlp_kernel<<<grid, 256, SMEM_BYTES>>>(x, W1, b1, W2, b2, out);
}

// round 4
// speedup vs baseline: 3.4363x; 1.2689x over previous
#include <cuda_runtime.h>
#include <cuda_bf16.h>
#include <cstdint>

#define NT      17
#define DIN     128
#define NNODES  32768
#define ROWS    128
#define TILES   (NNODES / ROWS)   // 256

#define S_STRIDE 136              // fp32 tile stride (floats): conflict-free LDS.64 A-frags
#define W_STRIDE 136              // packed-W stride (u32):     conflict-free LDS.32 B-frags
#define WBUF_U32 (16 * W_STRIDE)  // one K=32 slab (16 k2-rows)

#define S_FLOATS  (ROWS * S_STRIDE)
#define SMEM_BYTES (S_FLOATS * 4 + 4 * WBUF_U32 * 4 + ROWS * 4)

#define WELEMS (NT * 64 * 128)    // per-layer packed u32 count: 17*8192 = 139264

// ---------------- allocation-free scratch ----------------
__device__ int g_count[NT];
__device__ int g_idx[NT * NNODES];
__device__ uint32_t g_w1hi[WELEMS];
__device__ uint32_t g_w1lo[WELEMS];
__device__ uint32_t g_w2hi[WELEMS];
__device__ uint32_t g_w2lo[WELEMS];

// ---------------- helpers ----------------
__device__ __forceinline__ void split2(float2 p, uint32_t& hi, uint32_t& lo) {
    __nv_bfloat162 h = __float22bfloat162_rn(p);
    float2 lf = make_float2(p.x - __bfloat162float(h.x), p.y - __bfloat162float(h.y));
    __nv_bfloat162 l = __float22bfloat162_rn(lf);
    hi = *reinterpret_cast<uint32_t*>(&h);
    lo = *reinterpret_cast<uint32_t*>(&l);
}

__device__ __forceinline__ void mma_bf16(float* c, const uint32_t* a, const uint32_t* b) {
    asm volatile(
        "mma.sync.aligned.m16n8k16.row.col.f32.bf16.bf16.f32 "
        "{%0,%1,%2,%3}, {%4,%5,%6,%7}, {%8,%9}, {%0,%1,%2,%3};"
        : "+f"(c[0]), "+f"(c[1]), "+f"(c[2]), "+f"(c[3])
        : "r"(a[0]), "r"(a[1]), "r"(a[2]), "r"(a[3]), "r"(b[0]), "r"(b[1]));
}

// ---------------- prep: zero counts + split W into packed bf16 hi/lo ----------------
// Packed layout per layer: [t][k2][n] u32, where u32 = bf16x2 {low = W[2*k2][n], high = W[2*k2+1][n]}.
__global__ void prep_kernel(const float* __restrict__ W1, const float* __restrict__ W2) {
    if (blockIdx.x == 0 && threadIdx.x < NT) g_count[threadIdx.x] = 0;
    int idx = blockIdx.x * 256 + threadIdx.x;       // grid sized exactly WELEMS/256
    int t   = idx >> 13;
    int rem = idx & 8191;
    int k2  = rem >> 7;
    int n   = rem & 127;
    size_t off = (size_t)t * 16384 + (size_t)k2 * 256 + n;
    {
        float a0 = __ldg(W1 + off), a1 = __ldg(W1 + off + 128);
        uint32_t hi, lo;
        split2(make_float2(a0, a1), hi, lo);
        g_w1hi[idx] = hi; g_w1lo[idx] = lo;
    }
    {
        float a0 = __ldg(W2 + off), a1 = __ldg(W2 + off + 128);
        uint32_t hi, lo;
        split2(make_float2(a0, a1), hi, lo);
        g_w2hi[idx] = hi; g_w2lo[idx] = lo;
    }
}

__global__ void scatter_kernel(const int* __restrict__ types) {
    int n = blockIdx.x * blockDim.x + threadIdx.x;
    if (n < NNODES) {
        int t = types[n];
        int p = atomicAdd(&g_count[t], 1);
        g_idx[t * NNODES + p] = n;
    }
}

// ---------------- staging: copy one K=32 slab (hi+lo) from global into smem ----------------
__device__ __forceinline__ void stage(const uint32_t* __restrict__ ghi,
                                      const uint32_t* __restrict__ glo,
                                      int st, uint32_t* WhB, uint32_t* WlB, int tid) {
    #pragma unroll
    for (int i = 0; i < 2; i++) {
        int li  = tid + i * 256;        // uint4 index 0..511
        int row = li >> 5;              // 0..15
        int nc  = (li & 31) << 2;       // 0..124
        uint4 vh = __ldg(reinterpret_cast<const uint4*>(ghi + (st * 16 + row) * 128 + nc));
        uint4 vl = __ldg(reinterpret_cast<const uint4*>(glo + (st * 16 + row) * 128 + nc));
        *reinterpret_cast<uint4*>(WhB + row * W_STRIDE + nc) = vh;
        *reinterpret_cast<uint4*>(WlB + row * W_STRIDE + nc) = vl;
    }
}

// ---------------- one 128x128x128 GEMM (bf16x3 split), acc += S @ W ----------------
__device__ __forceinline__ void gemm128(const uint32_t* __restrict__ ghi,
                                        const uint32_t* __restrict__ glo,
                                        const float* S, uint32_t* Wh, uint32_t* Wl,
                                        float acc[2][8][4],
                                        int tid, int lane, int mbase, int nbase) {
    stage(ghi, glo, 0, Wh, Wl, tid);
    __syncthreads();

    #pragma unroll 1
    for (int st = 0; st < 4; st++) {
        int cur = st & 1;
        if (st < 3)
            stage(ghi, glo, st + 1, Wh + (1 - cur) * WBUF_U32, Wl + (1 - cur) * WBUF_U32, tid);

        const uint32_t* WhC = Wh + cur * WBUF_U32;
        const uint32_t* WlC = Wl + cur * WBUF_U32;

        #pragma unroll
        for (int c = 0; c < 2; c++) {      // two k16 chunks per slab
            int kbase = st * 32 + c * 16;

            // A fragments: fp32 from S -> bf16 hi/lo in regs
            uint32_t ahi[2][4], alo[2][4];
            int k0 = kbase + 2 * (lane & 3);
            #pragma unroll
            for (int s = 0; s < 2; s++) {
                int r = mbase + s * 16 + (lane >> 2);
                float2 p0 = *reinterpret_cast<const float2*>(S + r * S_STRIDE + k0);
                float2 p1 = *reinterpret_cast<const float2*>(S + (r + 8) * S_STRIDE + k0);
                float2 p2 = *reinterpret_cast<const float2*>(S + r * S_STRIDE + k0 + 8);
                float2 p3 = *reinterpret_cast<const float2*>(S + (r + 8) * S_STRIDE + k0 + 8);
                split2(p0, ahi[s][0], alo[s][0]);
                split2(p1, ahi[s][1], alo[s][1]);
                split2(p2, ahi[s][2], alo[s][2]);
                split2(p3, ahi[s][3], alo[s][3]);
            }

            int k2r = c * 8 + (lane & 3);
            #pragma unroll
            for (int nt = 0; nt < 8; nt++) {
                int col = nbase + nt * 8 + (lane >> 2);
                uint32_t bh[2], bl[2];
                bh[0] = WhC[k2r * W_STRIDE + col];
                bh[1] = WhC[(k2r + 4) * W_STRIDE + col];
                bl[0] = WlC[k2r * W_STRIDE + col];
                bl[1] = WlC[(k2r + 4) * W_STRIDE + col];
                #pragma unroll
                for (int s = 0; s < 2; s++) {
                    mma_bf16(acc[s][nt], ahi[s], bh);
                    mma_bf16(acc[s][nt], ahi[s], bl);
                    mma_bf16(acc[s][nt], alo[s], bh);
                }
            }
        }
        __syncthreads();
    }
}

extern __shared__ __align__(16) float smem[];

__global__ __launch_bounds__(256, 2) void mlp_kernel(
    const float* __restrict__ x,
    const float* __restrict__ b1,
    const float* __restrict__ b2,
    float* __restrict__ out)
{
    float*    S  = smem;
    uint32_t* Wh = reinterpret_cast<uint32_t*>(S + S_FLOATS);
    uint32_t* Wl = Wh + 2 * WBUF_U32;
    int* rowidx  = reinterpret_cast<int*>(Wl + 2 * WBUF_U32);

    const int t    = blockIdx.y;
    const int cnt  = g_count[t];
    const int base = blockIdx.x * ROWS;
    if (base >= cnt) return;

    const int tid   = threadIdx.x;
    const int lane  = tid & 31;
    const int warp  = tid >> 5;
    const int mbase = (warp >> 1) * 32;
    const int nbase = (warp & 1) * 64;

    if (tid < ROWS) {
        int r = base + tid;
        rowidx[tid] = (r < cnt) ? g_idx[t * NNODES + r] : -1;
    }
    __syncthreads();

    // Gather x rows into S (thread -> half a row via 16 float4s)
    {
        int r = tid >> 1, half = tid & 1;
        int g = rowidx[r];
        float4* dst = reinterpret_cast<float4*>(S + r * S_STRIDE + half * 64);
        if (g >= 0) {
            const float4* src = reinterpret_cast<const float4*>(x + (size_t)g * DIN + half * 64);
            #pragma unroll
            for (int i = 0; i < 16; i++) dst[i] = __ldg(src + i);
        } else {
            #pragma unroll
            for (int i = 0; i < 16; i++) dst[i] = make_float4(0.f, 0.f, 0.f, 0.f);
        }
    }
    // (first sync inside gemm128 covers the gather)

    float acc[2][8][4];
    #pragma unroll
    for (int s = 0; s < 2; s++)
        #pragma unroll
        for (int nt = 0; nt < 8; nt++)
            #pragma unroll
            for (int i = 0; i < 4; i++) acc[s][nt][i] = 0.f;

    // ---------------- Layer 1 ----------------
    gemm128(g_w1hi + t * 8192, g_w1lo + t * 8192, S, Wh, Wl, acc, tid, lane, mbase, nbase);

    // bias + relu -> write H back into S
    #pragma unroll
    for (int s = 0; s < 2; s++) {
        #pragma unroll
        for (int nt = 0; nt < 8; nt++) {
            int col = nbase + nt * 8 + 2 * (lane & 3);
            float bb0 = __ldg(b1 + t * DIN + col);
            float bb1 = __ldg(b1 + t * DIN + col + 1);
            int r0 = mbase + s * 16 + (lane >> 2);
            float2 v0 = make_float2(fmaxf(acc[s][nt][0] + bb0, 0.f),
                                    fmaxf(acc[s][nt][1] + bb1, 0.f));
            float2 v1 = make_float2(fmaxf(acc[s][nt][2] + bb0, 0.f),
                                    fmaxf(acc[s][nt][3] + bb1, 0.f));
            *reinterpret_cast<float2*>(S + r0 * S_STRIDE + col)       = v0;
            *reinterpret_cast<float2*>(S + (r0 + 8) * S_STRIDE + col) = v1;
            acc[s][nt][0] = acc[s][nt][1] = acc[s][nt][2] = acc[s][nt][3] = 0.f;
        }
    }
    // (sync inside second gemm128 orders these writes before reads)

    // ---------------- Layer 2 ----------------
    gemm128(g_w2hi + t * 8192, g_w2lo + t * 8192, S, Wh, Wl, acc, tid, lane, mbase, nbase);

    // bias -> scatter to out
    #pragma unroll
    for (int s = 0; s < 2; s++) {
        #pragma unroll
        for (int nt = 0; nt < 8; nt++) {
            int col = nbase + nt * 8 + 2 * (lane & 3);
            float bb0 = __ldg(b2 + t * DIN + col);
            float bb1 = __ldg(b2 + t * DIN + col + 1);
            int r0 = mbase + s * 16 + (lane >> 2);
            int g0 = rowidx[r0];
            int g1 = rowidx[r0 + 8];
            if (g0 >= 0) {
                float2 v = make_float2(acc[s][nt][0] + bb0, acc[s][nt][1] + bb1);
                *reinterpret_cast<float2*>(out + (size_t)g0 * DIN + col) = v;
            }
            if (g1 >= 0) {
                float2 v = make_float2(acc[s][nt][2] + bb0, acc[s][nt][3] + bb1);
                *reinterpret_cast<float2*>(out + (size_t)g1 * DIN + col) = v;
            }
        }
    }
}

extern "C" void kernel_launch(void* const* d_in, const int* in_sizes, int n_in,
                              void* d_out, int out_size)
{
    const float* x     = (const float*)d_in[0];
    const float* W1    = (const float*)d_in[1];
    const float* b1    = (const float*)d_in[2];
    const float* W2    = (const float*)d_in[3];
    const float* b2    = (const float*)d_in[4];
    const int*   types = (const int*)  d_in[5];
    float*       out   = (float*)d_out;

    cudaFuncSetAttribute(mlp_kernel, cudaFuncAttributeMaxDynamicSharedMemorySize, SMEM_BYTES);

    prep_kernel<<<WELEMS / 256, 256>>>(W1, W2);
    scatter_kernel<<<NNODES / 256, 256>>>(types);
    dim3 grid(TILES, NT);
    mlp_kernel<<<grid, 256, SMEM_BYTES>>>(x, b1, b2, out);
}